// round 2
// baseline (speedup 1.0000x reference)
#include <cuda_runtime.h>
#include <cstddef>
#include <math.h>

// ---------------------------------------------------------------------------
// SpatialTranscriptomicsDecoder — fp32, GB300 sm_103a. Round 2.
// SGEMM v2: duplicated-A smem (f32x2 vector loads), double-buffered, 1 barrier
// per k-step, BM template {64,32} for large/small M.
// ---------------------------------------------------------------------------

static constexpr int B = 2, P = 196, FD = 1024, G = 2000, D = 256, H = 8, NL = 4, HALF = 128;
static constexpr float ATT_SCALE = 0.17677669529663687f; // 1/sqrt(32)

static constexpr size_t OFF_PATCH = 0;
static constexpr size_t OFF_TMP   = OFF_PATCH + (size_t)B * P * D;
static constexpr size_t OFF_PE    = OFF_TMP   + (size_t)B * P * D;
static constexpr size_t OFF_KV    = OFF_PE    + (size_t)B * P * D;
static constexpr size_t OFF_Q     = OFF_KV    + (size_t)B * P * 2 * D;
static constexpr size_t OFF_QB    = OFF_Q     + (size_t)B * G * D;
static constexpr size_t OFF_CTX   = OFF_QB    + (size_t)B * G * D;
static constexpr size_t OFF_ATT   = OFF_CTX   + (size_t)B * G * D;
static constexpr size_t OFF_FFH   = OFF_ATT   + (size_t)B * G * D;
static constexpr size_t OFF_QP    = OFF_FFH   + (size_t)B * G * 4 * D;
static constexpr size_t OFF_PP    = OFF_QP    + (size_t)B * G * HALF;
static constexpr size_t WS_TOTAL  = OFF_PP    + (size_t)B * P * HALF;

__device__ float g_ws[WS_TOTAL];

__device__ __forceinline__ float geluf(float x) {
    return 0.5f * x * (1.0f + erff(x * 0.7071067811865476f));
}
__device__ __forceinline__ float softplusf(float x) {
    return fmaxf(x, 0.0f) + __logf(1.0f + __expf(-fabsf(x)));
}
__device__ __forceinline__ float2 u2f2(unsigned long long u) {
    float2 f;
    asm("mov.b64 {%0, %1}, %2;" : "=f"(f.x), "=f"(f.y) : "l"(u));
    return f;
}
__device__ __forceinline__ void fma2(unsigned long long& acc, unsigned long long a,
                                     unsigned long long b) {
    asm("fma.rn.f32x2 %0, %1, %2, %0;" : "+l"(acc) : "l"(a), "l"(b));
}

// ---------------------------------------------------------------------------
// C[M,N] = act( A[M,K] @ W[N,K]^T + bias[N] + (R ? R[M,N] : 0) )
// N % 64 == 0, K % 16 == 0. act: 0 none, 1 exact GELU.
// BM in {64, 32}. Block = 256 threads, tile BM x 64, k-step 16, double-buffered.
// A is stored duplicated in smem: Asd[k][m] = (a, a) so the f32x2 inner loop is
// pure vector LDS: 2xLDS.128(A) + 2xLDS.64(W) + 8 FMA2 per kk (BM=64).
// ---------------------------------------------------------------------------
template<int BM>
__global__ void __launch_bounds__(256) sgemm_kernel(
    const float* __restrict__ A, const float* __restrict__ W,
    const float* __restrict__ bias, const float* __restrict__ R,
    float* __restrict__ C, int M, int N, int K, int act)
{
    constexpr int RPT = BM / 16;                 // rows per thread: 4 or 2
    __shared__ __align__(16) float2 Asd[2][16][BM + 2];
    __shared__ __align__(16) float  Ws [2][16][68];

    const int tid = threadIdx.x;
    const int tx = tid & 15;                     // -> N (4 cols)
    const int ty = tid >> 4;                     // -> M (RPT rows)
    const int bm = blockIdx.y * BM;
    const int bn = blockIdx.x * 64;

    // W loader: 64 rows x 16 k / 256 thr = float4 each
    const int lrW = tid >> 2;
    const int lcW = (tid & 3) << 2;
    const float* Wp = W + (size_t)(bn + lrW) * K + lcW;

    // A loader
    int lrA, lcA;
    if (BM == 64) { lrA = tid >> 2;  lcA = (tid & 3) << 2; }   // float4
    else          { lrA = tid >> 3;  lcA = (tid & 7) << 1; }   // float2
    const bool a_ok = (bm + lrA) < M;
    const float* Ap = A + (size_t)(bm + lrA) * K + lcA;

    unsigned long long acc[RPT][2];
#pragma unroll
    for (int i = 0; i < RPT; i++) { acc[i][0] = 0ull; acc[i][1] = 0ull; }

    float4 av4 = make_float4(0.f,0.f,0.f,0.f), wv4;
    float2 av2 = make_float2(0.f,0.f);

    // prologue: load k0 = 0 and stage into buffer 0
    if (BM == 64) { if (a_ok) av4 = *(const float4*)(Ap); }
    else          { if (a_ok) av2 = *(const float2*)(Ap); }
    wv4 = *(const float4*)(Wp);
    if (BM == 64) {
        Asd[0][lcA + 0][lrA] = make_float2(av4.x, av4.x);
        Asd[0][lcA + 1][lrA] = make_float2(av4.y, av4.y);
        Asd[0][lcA + 2][lrA] = make_float2(av4.z, av4.z);
        Asd[0][lcA + 3][lrA] = make_float2(av4.w, av4.w);
    } else {
        Asd[0][lcA + 0][lrA] = make_float2(av2.x, av2.x);
        Asd[0][lcA + 1][lrA] = make_float2(av2.y, av2.y);
    }
    Ws[0][lcW + 0][lrW] = wv4.x;
    Ws[0][lcW + 1][lrW] = wv4.y;
    Ws[0][lcW + 2][lrW] = wv4.z;
    Ws[0][lcW + 3][lrW] = wv4.w;
    __syncthreads();

    const int niter = K >> 4;
    int buf = 0;
    for (int it = 0; it < niter; it++) {
        const bool pre = (it + 1) < niter;
        if (pre) {
            const int ko = (it + 1) << 4;
            if (BM == 64) { if (a_ok) av4 = *(const float4*)(Ap + ko); }
            else          { if (a_ok) av2 = *(const float2*)(Ap + ko); }
            wv4 = *(const float4*)(Wp + ko);
        }
#pragma unroll
        for (int kk = 0; kk < 16; kk++) {
            unsigned long long b0 = *(const unsigned long long*)&Ws[buf][kk][tx << 2];
            unsigned long long b1 = *(const unsigned long long*)&Ws[buf][kk][(tx << 2) + 2];
            if (BM == 64) {
                ulonglong2 aA = *(const ulonglong2*)&Asd[buf][kk][ty << 2];
                ulonglong2 aB = *(const ulonglong2*)&Asd[buf][kk][(ty << 2) + 2];
                fma2(acc[0][0], aA.x, b0); fma2(acc[0][1], aA.x, b1);
                fma2(acc[1][0], aA.y, b0); fma2(acc[1][1], aA.y, b1);
                fma2(acc[2][0], aB.x, b0); fma2(acc[2][1], aB.x, b1);
                fma2(acc[3][0], aB.y, b0); fma2(acc[3][1], aB.y, b1);
            } else {
                ulonglong2 aA = *(const ulonglong2*)&Asd[buf][kk][ty << 1];
                fma2(acc[0][0], aA.x, b0); fma2(acc[0][1], aA.x, b1);
                fma2(acc[1][0], aA.y, b0); fma2(acc[1][1], aA.y, b1);
            }
        }
        if (pre) {
            const int nb = buf ^ 1;
            if (BM == 64) {
                Asd[nb][lcA + 0][lrA] = make_float2(av4.x, av4.x);
                Asd[nb][lcA + 1][lrA] = make_float2(av4.y, av4.y);
                Asd[nb][lcA + 2][lrA] = make_float2(av4.z, av4.z);
                Asd[nb][lcA + 3][lrA] = make_float2(av4.w, av4.w);
            } else {
                Asd[nb][lcA + 0][lrA] = make_float2(av2.x, av2.x);
                Asd[nb][lcA + 1][lrA] = make_float2(av2.y, av2.y);
            }
            Ws[nb][lcW + 0][lrW] = wv4.x;
            Ws[nb][lcW + 1][lrW] = wv4.y;
            Ws[nb][lcW + 2][lrW] = wv4.z;
            Ws[nb][lcW + 3][lrW] = wv4.w;
            __syncthreads();
            buf = nb;
        }
    }

    const int col0 = bn + (tx << 2);
    float4 b4 = make_float4(0.f, 0.f, 0.f, 0.f);
    if (bias) b4 = *(const float4*)(bias + col0);
#pragma unroll
    for (int i = 0; i < RPT; i++) {
        int row = bm + ty * RPT + i;
        if (row >= M) continue;
        float2 v0 = u2f2(acc[i][0]);
        float2 v1 = u2f2(acc[i][1]);
        float4 o;
        o.x = v0.x + b4.x; o.y = v0.y + b4.y; o.z = v1.x + b4.z; o.w = v1.y + b4.w;
        if (R) {
            float4 r4 = *(const float4*)(R + (size_t)row * N + col0);
            o.x += r4.x; o.y += r4.y; o.z += r4.z; o.w += r4.w;
        }
        if (act == 1) {
            o.x = geluf(o.x); o.y = geluf(o.y); o.z = geluf(o.z); o.w = geluf(o.w);
        }
        *(float4*)(C + (size_t)row * N + col0) = o;
    }
}

// ---------------------------------------------------------------------------
// y[row] = LayerNorm( x[row] + (r ? r[row] : 0) ) * g + b, width 256. warp/row.
// ---------------------------------------------------------------------------
__global__ void ln_kernel(const float* __restrict__ x, const float* __restrict__ r,
                          const float* __restrict__ gg, const float* __restrict__ bb,
                          float* __restrict__ y, int rows)
{
    int gid = blockIdx.x * blockDim.x + threadIdx.x;
    int row = gid >> 5;
    int lane = gid & 31;
    if (row >= rows) return;
    const float* xp = x + (size_t)row * 256;
    float4 a = *(const float4*)(xp + lane * 4);
    float4 c = *(const float4*)(xp + 128 + lane * 4);
    if (r) {
        const float* rp = r + (size_t)row * 256;
        float4 ra = *(const float4*)(rp + lane * 4);
        float4 rc = *(const float4*)(rp + 128 + lane * 4);
        a.x += ra.x; a.y += ra.y; a.z += ra.z; a.w += ra.w;
        c.x += rc.x; c.y += rc.y; c.z += rc.z; c.w += rc.w;
    }
    float s = a.x + a.y + a.z + a.w + c.x + c.y + c.z + c.w;
    float q = a.x * a.x + a.y * a.y + a.z * a.z + a.w * a.w
            + c.x * c.x + c.y * c.y + c.z * c.z + c.w * c.w;
#pragma unroll
    for (int o = 16; o; o >>= 1) {
        s += __shfl_xor_sync(0xffffffffu, s, o);
        q += __shfl_xor_sync(0xffffffffu, q, o);
    }
    float mean = s * (1.f / 256.f);
    float var = q * (1.f / 256.f) - mean * mean;
    float rstd = rsqrtf(var + 1e-5f);
    float4 g0 = *(const float4*)(gg + lane * 4);
    float4 g1 = *(const float4*)(gg + 128 + lane * 4);
    float4 b0 = *(const float4*)(bb + lane * 4);
    float4 b1 = *(const float4*)(bb + 128 + lane * 4);
    float4 o0, o1;
    o0.x = (a.x - mean) * rstd * g0.x + b0.x;
    o0.y = (a.y - mean) * rstd * g0.y + b0.y;
    o0.z = (a.z - mean) * rstd * g0.z + b0.z;
    o0.w = (a.w - mean) * rstd * g0.w + b0.w;
    o1.x = (c.x - mean) * rstd * g1.x + b1.x;
    o1.y = (c.y - mean) * rstd * g1.y + b1.y;
    o1.z = (c.z - mean) * rstd * g1.z + b1.z;
    o1.w = (c.w - mean) * rstd * g1.w + b1.w;
    float* yp = y + (size_t)row * 256;
    *(float4*)(yp + lane * 4) = o0;
    *(float4*)(yp + 128 + lane * 4) = o1;
}

__global__ void pe_kernel(const int* __restrict__ coords, const float* __restrict__ re,
                          const float* __restrict__ ce, float* __restrict__ pe)
{
    int idx = blockIdx.x * blockDim.x + threadIdx.x;
    if (idx >= B * P * D) return;
    int d = idx & 255;
    int bp = idx >> 8;
    int r = coords[bp * 2 + 0];
    int c = coords[bp * 2 + 1];
    r = min(max(r, 0), 255);
    c = min(max(c, 0), 255);
    pe[idx] = (d < 128) ? re[r * 128 + d] : ce[c * 128 + (d - 128)];
}

__global__ void qinit_kernel(const float* __restrict__ gq, float* __restrict__ q)
{
    int idx = blockIdx.x * blockDim.x + threadIdx.x;
    if (idx >= B * G * D) return;
    q[idx] = gq[idx % (G * D)];
}

// ---------------------------------------------------------------------------
// Cross-attention: grid (B*H, ceil(G/32)), block 256 (8 warps, 4 queries/warp)
// ---------------------------------------------------------------------------
__global__ void __launch_bounds__(256) attn_kernel(
    const float* __restrict__ Q, const float* __restrict__ KV, float* __restrict__ ctx)
{
    __shared__ float Kt[32][196];
    const int bh = blockIdx.x;
    const int b = bh >> 3, h = bh & 7;
    const int tid = threadIdx.x;
    const int lane = tid & 31, w = tid >> 5;

    const float* KVb = KV + (size_t)b * P * 512;
    for (int i = tid; i < P * 32; i += 256) {
        int p = i >> 5, d = i & 31;
        Kt[d][p] = KVb[(size_t)p * 512 + h * 32 + d] * ATT_SCALE;
    }
    __syncthreads();

    const int g0 = (blockIdx.y * 8 + w) * 4;
    if (g0 >= G) return;

    float qr[4];
#pragma unroll
    for (int i = 0; i < 4; i++)
        qr[i] = Q[(size_t)(b * G + g0 + i) * 256 + h * 32 + lane];

    float sc[4][7];
#pragma unroll
    for (int i = 0; i < 4; i++)
#pragma unroll
        for (int j = 0; j < 7; j++) sc[i][j] = 0.f;

#pragma unroll 4
    for (int d = 0; d < 32; d++) {
        float k0 = Kt[d][lane];
        float k1 = Kt[d][32 + lane];
        float k2 = Kt[d][64 + lane];
        float k3 = Kt[d][96 + lane];
        float k4 = Kt[d][128 + lane];
        float k5 = Kt[d][160 + lane];
        float k6 = (lane < 4) ? Kt[d][192 + lane] : 0.f;
#pragma unroll
        for (int i = 0; i < 4; i++) {
            float qd = __shfl_sync(0xffffffffu, qr[i], d);
            sc[i][0] = fmaf(qd, k0, sc[i][0]);
            sc[i][1] = fmaf(qd, k1, sc[i][1]);
            sc[i][2] = fmaf(qd, k2, sc[i][2]);
            sc[i][3] = fmaf(qd, k3, sc[i][3]);
            sc[i][4] = fmaf(qd, k4, sc[i][4]);
            sc[i][5] = fmaf(qd, k5, sc[i][5]);
            sc[i][6] = fmaf(qd, k6, sc[i][6]);
        }
    }

#pragma unroll
    for (int i = 0; i < 4; i++) {
        if (lane >= 4) sc[i][6] = -1e30f;
        float m = sc[i][0];
#pragma unroll
        for (int j = 1; j < 7; j++) m = fmaxf(m, sc[i][j]);
#pragma unroll
        for (int o = 16; o; o >>= 1) m = fmaxf(m, __shfl_xor_sync(0xffffffffu, m, o));
        float s = 0.f;
#pragma unroll
        for (int j = 0; j < 7; j++) { float e = __expf(sc[i][j] - m); sc[i][j] = e; s += e; }
#pragma unroll
        for (int o = 16; o; o >>= 1) s += __shfl_xor_sync(0xffffffffu, s, o);
        float inv = 1.0f / s;
#pragma unroll
        for (int j = 0; j < 7; j++) sc[i][j] *= inv;
    }

    float cx[4] = {0.f, 0.f, 0.f, 0.f};
    const float* Vb = KVb + 256 + h * 32 + lane;
#pragma unroll
    for (int jj = 0; jj < 7; jj++) {
        const int kmax = (jj == 6) ? 4 : 32;
        for (int src = 0; src < kmax; src++) {
            float v = Vb[(size_t)(jj * 32 + src) * 512];
#pragma unroll
            for (int i = 0; i < 4; i++) {
                float a = __shfl_sync(0xffffffffu, sc[i][jj], src);
                cx[i] = fmaf(a, v, cx[i]);
            }
        }
    }
#pragma unroll
    for (int i = 0; i < 4; i++)
        ctx[(size_t)(b * G + g0 + i) * 256 + h * 32 + lane] = cx[i];
}

// ---------------------------------------------------------------------------
// out[b,p,g,:] = softplus(q_proj[b,g,:] + p_proj[b,p,:])
// ---------------------------------------------------------------------------
__global__ void __launch_bounds__(256) head_kernel(
    const float* __restrict__ qp, const float* __restrict__ pp, float* __restrict__ out)
{
    const int bp = blockIdx.y;
    const int b = (bp >= P) ? 1 : 0;
    const int g = blockIdx.x * 8 + (threadIdx.x >> 5);
    const int hh = (threadIdx.x & 31) << 2;
    float4 pv = *(const float4*)(pp + (size_t)bp * HALF + hh);
    float4 qv = *(const float4*)(qp + (size_t)(b * G + g) * HALF + hh);
    float4 o;
    o.x = softplusf(pv.x + qv.x);
    o.y = softplusf(pv.y + qv.y);
    o.z = softplusf(pv.z + qv.z);
    o.w = softplusf(pv.w + qv.w);
    *(float4*)(out + ((size_t)bp * G + g) * HALF + hh) = o;
}

// ---------------------------------------------------------------------------
static inline void sgemm(const float* A, const float* W, const float* bias, const float* R,
                         float* C, int M, int N, int K, int act)
{
    if (M >= 1024) {
        dim3 grid(N / 64, (M + 63) / 64);
        sgemm_kernel<64><<<grid, 256>>>(A, W, bias, R, C, M, N, K, act);
    } else {
        dim3 grid(N / 64, (M + 31) / 32);
        sgemm_kernel<32><<<grid, 256>>>(A, W, bias, R, C, M, N, K, act);
    }
}

static inline void ln(const float* x, const float* r, const float* g, const float* b,
                      float* y, int rows)
{
    ln_kernel<<<(rows + 7) / 8, 256>>>(x, r, g, b, y, rows);
}

extern "C" void kernel_launch(void* const* d_in, const int* in_sizes, int n_in,
                              void* d_out, int out_size)
{
    (void)in_sizes; (void)n_in; (void)out_size;
    const float* patch_features = (const float*)d_in[0];
    const int*   patch_coords   = (const int*)d_in[1];
    const float* patch_proj_w   = (const float*)d_in[2];
    const float* patch_proj_b   = (const float*)d_in[3];
    const float* patch_ln_g     = (const float*)d_in[4];
    const float* patch_ln_b     = (const float*)d_in[5];
    const float* row_embed      = (const float*)d_in[6];
    const float* col_embed      = (const float*)d_in[7];
    const float* pe_proj_w      = (const float*)d_in[8];
    const float* pe_proj_b      = (const float*)d_in[9];
    const float* gene_queries   = (const float*)d_in[10];
    const float* in_proj_w      = (const float*)d_in[11];
    const float* in_proj_b      = (const float*)d_in[12];
    const float* out_w          = (const float*)d_in[13];
    const float* out_b          = (const float*)d_in[14];
    const float* ff1_w          = (const float*)d_in[15];
    const float* ff1_b          = (const float*)d_in[16];
    const float* ff2_w          = (const float*)d_in[17];
    const float* ff2_b          = (const float*)d_in[18];
    const float* ln1_g          = (const float*)d_in[19];
    const float* ln1_b          = (const float*)d_in[20];
    const float* ln2_g          = (const float*)d_in[21];
    const float* ln2_b          = (const float*)d_in[22];
    const float* head_w1        = (const float*)d_in[23];
    const float* head_b1        = (const float*)d_in[24];
    float* out = (float*)d_out;

    float* ws = nullptr;
    cudaGetSymbolAddress((void**)&ws, g_ws);
    float* patch_emb = ws + OFF_PATCH;
    float* tmp       = ws + OFF_TMP;
    float* pe        = ws + OFF_PE;
    float* kv        = ws + OFF_KV;
    float* q         = ws + OFF_Q;
    float* Qb        = ws + OFF_QB;
    float* ctx       = ws + OFF_CTX;
    float* att       = ws + OFF_ATT;
    float* ffh       = ws + OFF_FFH;
    float* qproj     = ws + OFF_QP;
    float* pproj     = ws + OFF_PP;

    const int MQ = B * G;  // 4000
    const int MP = B * P;  // 392

    // Stage A: patch embedding
    sgemm(patch_features, patch_proj_w, patch_proj_b, nullptr, tmp, MP, D, FD, 0);
    ln(tmp, nullptr, patch_ln_g, patch_ln_b, patch_emb, MP);
    pe_kernel<<<(B * P * D + 255) / 256, 256>>>(patch_coords, row_embed, col_embed, pe);
    sgemm(pe, pe_proj_w, pe_proj_b, patch_emb, patch_emb, MP, D, D, 0);
    qinit_kernel<<<(B * G * D + 255) / 256, 256>>>(gene_queries, q);

    // Stage B: decoder layers
    for (int l = 0; l < NL; l++) {
        const float* Wq  = in_proj_w + (size_t)l * 3 * D * D;
        const float* Wkv = Wq + (size_t)D * D;
        const float* bq  = in_proj_b + (size_t)l * 3 * D;
        const float* bkv = bq + D;
        sgemm(q, Wq, bq, nullptr, Qb, MQ, D, D, 0);
        sgemm(patch_emb, Wkv, bkv, nullptr, kv, MP, 2 * D, D, 0);
        attn_kernel<<<dim3(B * H, (G + 31) / 32), 256>>>(Qb, kv, ctx);
        sgemm(ctx, out_w + (size_t)l * D * D, out_b + (size_t)l * D, nullptr, att, MQ, D, D, 0);
        ln(q, att, ln1_g + (size_t)l * D, ln1_b + (size_t)l * D, q, MQ);
        sgemm(q, ff1_w + (size_t)l * 4 * D * D, ff1_b + (size_t)l * 4 * D, nullptr, ffh, MQ, 4 * D, D, 1);
        sgemm(ffh, ff2_w + (size_t)l * D * 4 * D, ff2_b + (size_t)l * D, nullptr, att, MQ, D, 4 * D, 0);
        ln(q, att, ln2_g + (size_t)l * D, ln2_b + (size_t)l * D, q, MQ);
    }

    // Stage C: head + broadcast softplus epilogue
    sgemm(q, head_w1, head_b1, nullptr, qproj, MQ, HALF, D, 0);
    sgemm(patch_emb, head_w1, nullptr, nullptr, pproj, MP, HALF, D, 0);
    head_kernel<<<dim3(G / 8, B * P), 256>>>(qproj, pproj, out);
}

// round 4
// speedup vs baseline: 1.2485x; 1.2485x over previous
#include <cuda_runtime.h>
#include <cstddef>
#include <cstdint>
#include <math.h>

// ---------------------------------------------------------------------------
// SpatialTranscriptomicsDecoder — fp32, GB300 sm_103a. Round 4 (R3 + include fix).
// R1 inner loop (proven) + 4-stage cp.async pipeline + one-time weight
// transpose so both A and W tiles load via 16B cp.async (latency hidden).
// ---------------------------------------------------------------------------

static constexpr int B = 2, P = 196, FD = 1024, G = 2000, D = 256, H = 8, NL = 4, HALF = 128;
static constexpr float ATT_SCALE = 0.17677669529663687f; // 1/sqrt(32)

// activation workspace (floats)
static constexpr size_t OFF_PATCH = 0;
static constexpr size_t OFF_TMP   = OFF_PATCH + (size_t)B * P * D;
static constexpr size_t OFF_PE    = OFF_TMP   + (size_t)B * P * D;
static constexpr size_t OFF_KV    = OFF_PE    + (size_t)B * P * D;
static constexpr size_t OFF_Q     = OFF_KV    + (size_t)B * P * 2 * D;
static constexpr size_t OFF_QB    = OFF_Q     + (size_t)B * G * D;
static constexpr size_t OFF_CTX   = OFF_QB    + (size_t)B * G * D;
static constexpr size_t OFF_ATT   = OFF_CTX   + (size_t)B * G * D;
static constexpr size_t OFF_FFH   = OFF_ATT   + (size_t)B * G * D;
static constexpr size_t OFF_QP    = OFF_FFH   + (size_t)B * G * 4 * D;
static constexpr size_t OFF_PP    = OFF_QP    + (size_t)B * G * HALF;
// transposed weights
static constexpr size_t OFF_WT_PATCH = OFF_PP + (size_t)B * P * HALF;
static constexpr size_t OFF_WT_PE    = OFF_WT_PATCH + 256 * 1024;
static constexpr size_t OFF_WT_WQ    = OFF_WT_PE    + 256 * 256;
static constexpr size_t OFF_WT_WKV   = OFF_WT_WQ    + (size_t)NL * 256 * 256;
static constexpr size_t OFF_WT_OUT   = OFF_WT_WKV   + (size_t)NL * 512 * 256;
static constexpr size_t OFF_WT_FF1   = OFF_WT_OUT   + (size_t)NL * 256 * 256;
static constexpr size_t OFF_WT_FF2   = OFF_WT_FF1   + (size_t)NL * 1024 * 256;
static constexpr size_t OFF_WT_HEAD  = OFF_WT_FF2   + (size_t)NL * 256 * 1024;
static constexpr size_t WS_TOTAL     = OFF_WT_HEAD  + 128 * 256;

__device__ float g_ws[WS_TOTAL];

__device__ __forceinline__ float geluf(float x) {
    return 0.5f * x * (1.0f + erff(x * 0.7071067811865476f));
}
__device__ __forceinline__ float softplusf(float x) {
    return fmaxf(x, 0.0f) + __logf(1.0f + __expf(-fabsf(x)));
}
__device__ __forceinline__ float2 u2f2(unsigned long long u) {
    float2 f;
    asm("mov.b64 {%0, %1}, %2;" : "=f"(f.x), "=f"(f.y) : "l"(u));
    return f;
}
__device__ __forceinline__ void fma2(unsigned long long& acc, unsigned long long a,
                                     unsigned long long b) {
    asm("fma.rn.f32x2 %0, %1, %2, %0;" : "+l"(acc) : "l"(a), "l"(b));
}
__device__ __forceinline__ void cpa16(unsigned int dst, const float* src, bool ok) {
    asm volatile("cp.async.ca.shared.global [%0], [%1], 16, %2;"
                 :: "r"(dst), "l"(src), "r"(ok ? 16 : 0) : "memory");
}
__device__ __forceinline__ void cpa_commit() {
    asm volatile("cp.async.commit_group;" ::: "memory");
}
__device__ __forceinline__ void cpa_wait2() {
    asm volatile("cp.async.wait_group 2;" ::: "memory");
}

// ---------------------------------------------------------------------------
// one-shot weight transpose: src[N,K] row-major -> dst[K,N] row-major
// 23 segments in one launch; 32x32 smem tiles; all N,K multiples of 32.
// ---------------------------------------------------------------------------
struct TSeg { const float* src; float* dst; int N; int K; int tile_off; };
struct TTable { TSeg seg[23]; };

__global__ void __launch_bounds__(256) transpose_kernel(TTable t)
{
    __shared__ float sm[32][33];
    const int bt = blockIdx.x;
    int s = 0;
#pragma unroll
    for (int i = 1; i < 23; i++) if (t.seg[i].tile_off <= bt) s = i;
    const TSeg sg = t.seg[s];
    const int lt = bt - sg.tile_off;
    const int tk = sg.K >> 5;
    const int nr = (lt / tk) << 5;   // origin in N
    const int kc = (lt % tk) << 5;   // origin in K
    const int tx = threadIdx.x & 31, ty = threadIdx.x >> 5;
#pragma unroll
    for (int i = 0; i < 4; i++)
        sm[ty + i * 8][tx] = sg.src[(size_t)(nr + ty + i * 8) * sg.K + kc + tx];
    __syncthreads();
#pragma unroll
    for (int i = 0; i < 4; i++)
        sg.dst[(size_t)(kc + ty + i * 8) * sg.N + nr + tx] = sm[tx][ty + i * 8];
}

// ---------------------------------------------------------------------------
// C[M,N] = act( A[M,K] @ Wt[K,N] + bias[N] + (R ? R[M,N] : 0) )
// Wt is the TRANSPOSED weight (k-major). N%64==0, K%16==0. act: 0 none, 1 GELU.
// 256 threads, tile BM x 64, k-step 16, 4-stage cp.async pipeline.
// ---------------------------------------------------------------------------
template<int BM>
__global__ void __launch_bounds__(256) sgemm_kernel(
    const float* __restrict__ A, const float* __restrict__ Wt,
    const float* __restrict__ bias, const float* __restrict__ R,
    float* __restrict__ C, int M, int N, int K, int act)
{
    constexpr int RPT = BM / 16;
    constexpr int S = 4;
    __shared__ __align__(16) float As[S][BM][20];
    __shared__ __align__(16) float Ws[S][16][68];

    const int tid = threadIdx.x;
    const int tx = tid & 15;
    const int ty = tid >> 4;
    const int bm = blockIdx.y * BM;
    const int bn = blockIdx.x * 64;

    // W loader: 16 k-rows x 64 n / 16B -> every thread one cp
    const int kkW = tid >> 4;            // 0..15
    const int nW  = (tid & 15) << 2;     // 0..60
    const float* WtBase = Wt + (size_t)kkW * N + bn + nW;

    // A loader
    const int rA = tid >> 2;             // 0..63
    const int cA = (tid & 3) << 2;       // 0,4,8,12
    const bool a_thread = (BM == 64) ? true : (tid < 128);
    const bool a_ok = a_thread && (bm + rA) < M;
    const float* Ap = A + (size_t)(bm + rA) * K + cA;

    unsigned int sW[S], sA[S];
#pragma unroll
    for (int s = 0; s < S; s++) {
        sW[s] = (unsigned int)__cvta_generic_to_shared(&Ws[s][kkW][nW]);
        sA[s] = (unsigned int)__cvta_generic_to_shared(&As[s][(BM == 64) ? rA : (rA & (BM - 1))][cA]);
    }

    const int niter = K >> 4;

    // prologue: stages 0..S-2
#pragma unroll
    for (int s = 0; s < S - 1; s++) {
        const int k0 = s << 4;
        cpa16(sW[s], WtBase + (size_t)k0 * N, true);
        if (a_thread) cpa16(sA[s], Ap + k0, a_ok);
        cpa_commit();
    }

    unsigned long long acc[RPT][2];
#pragma unroll
    for (int i = 0; i < RPT; i++) { acc[i][0] = 0ull; acc[i][1] = 0ull; }

    for (int it = 0; it < niter; it++) {
        cpa_wait2();
        __syncthreads();
        // issue stage it+S-1 into buffer (it-1)%S (done being read)
        const int nit = it + S - 1;
        if (nit < niter) {
            const int nb = nit & (S - 1);
            const int k0 = nit << 4;
            cpa16(sW[nb], WtBase + (size_t)k0 * N, true);
            if (a_thread) cpa16(sA[nb], Ap + k0, a_ok);
        }
        cpa_commit();

        const int buf = it & (S - 1);
#pragma unroll
        for (int kk = 0; kk < 16; kk++) {
            ulonglong2 bb = *(const ulonglong2*)&Ws[buf][kk][tx << 2];
#pragma unroll
            for (int i = 0; i < RPT; i++) {
                float a = As[buf][ty * RPT + i][kk];
                unsigned long long a2;
                asm("mov.b64 %0, {%1, %1};" : "=l"(a2) : "f"(a));
                fma2(acc[i][0], a2, bb.x);
                fma2(acc[i][1], a2, bb.y);
            }
        }
    }

    const int col0 = bn + (tx << 2);
    float4 b4 = make_float4(0.f, 0.f, 0.f, 0.f);
    if (bias) b4 = *(const float4*)(bias + col0);
#pragma unroll
    for (int i = 0; i < RPT; i++) {
        int row = bm + ty * RPT + i;
        if (row >= M) continue;
        float2 v0 = u2f2(acc[i][0]);
        float2 v1 = u2f2(acc[i][1]);
        float4 o;
        o.x = v0.x + b4.x; o.y = v0.y + b4.y; o.z = v1.x + b4.z; o.w = v1.y + b4.w;
        if (R) {
            float4 r4 = *(const float4*)(R + (size_t)row * N + col0);
            o.x += r4.x; o.y += r4.y; o.z += r4.z; o.w += r4.w;
        }
        if (act == 1) {
            o.x = geluf(o.x); o.y = geluf(o.y); o.z = geluf(o.z); o.w = geluf(o.w);
        }
        *(float4*)(C + (size_t)row * N + col0) = o;
    }
}

// ---------------------------------------------------------------------------
// y[row] = LayerNorm( x[row] + (r ? r[row] : 0) ) * g + b, width 256. warp/row.
// ---------------------------------------------------------------------------
__global__ void ln_kernel(const float* __restrict__ x, const float* __restrict__ r,
                          const float* __restrict__ gg, const float* __restrict__ bb,
                          float* __restrict__ y, int rows)
{
    int gid = blockIdx.x * blockDim.x + threadIdx.x;
    int row = gid >> 5;
    int lane = gid & 31;
    if (row >= rows) return;
    const float* xp = x + (size_t)row * 256;
    float4 a = *(const float4*)(xp + lane * 4);
    float4 c = *(const float4*)(xp + 128 + lane * 4);
    if (r) {
        const float* rp = r + (size_t)row * 256;
        float4 ra = *(const float4*)(rp + lane * 4);
        float4 rc = *(const float4*)(rp + 128 + lane * 4);
        a.x += ra.x; a.y += ra.y; a.z += ra.z; a.w += ra.w;
        c.x += rc.x; c.y += rc.y; c.z += rc.z; c.w += rc.w;
    }
    float s = a.x + a.y + a.z + a.w + c.x + c.y + c.z + c.w;
    float q = a.x * a.x + a.y * a.y + a.z * a.z + a.w * a.w
            + c.x * c.x + c.y * c.y + c.z * c.z + c.w * c.w;
#pragma unroll
    for (int o = 16; o; o >>= 1) {
        s += __shfl_xor_sync(0xffffffffu, s, o);
        q += __shfl_xor_sync(0xffffffffu, q, o);
    }
    float mean = s * (1.f / 256.f);
    float var = q * (1.f / 256.f) - mean * mean;
    float rstd = rsqrtf(var + 1e-5f);
    float4 g0 = *(const float4*)(gg + lane * 4);
    float4 g1 = *(const float4*)(gg + 128 + lane * 4);
    float4 b0 = *(const float4*)(bb + lane * 4);
    float4 b1 = *(const float4*)(bb + 128 + lane * 4);
    float4 o0, o1;
    o0.x = (a.x - mean) * rstd * g0.x + b0.x;
    o0.y = (a.y - mean) * rstd * g0.y + b0.y;
    o0.z = (a.z - mean) * rstd * g0.z + b0.z;
    o0.w = (a.w - mean) * rstd * g0.w + b0.w;
    o1.x = (c.x - mean) * rstd * g1.x + b1.x;
    o1.y = (c.y - mean) * rstd * g1.y + b1.y;
    o1.z = (c.z - mean) * rstd * g1.z + b1.z;
    o1.w = (c.w - mean) * rstd * g1.w + b1.w;
    float* yp = y + (size_t)row * 256;
    *(float4*)(yp + lane * 4) = o0;
    *(float4*)(yp + 128 + lane * 4) = o1;
}

__global__ void pe_kernel(const int* __restrict__ coords, const float* __restrict__ re,
                          const float* __restrict__ ce, float* __restrict__ pe)
{
    int idx = blockIdx.x * blockDim.x + threadIdx.x;
    if (idx >= B * P * D) return;
    int d = idx & 255;
    int bp = idx >> 8;
    int r = coords[bp * 2 + 0];
    int c = coords[bp * 2 + 1];
    r = min(max(r, 0), 255);
    c = min(max(c, 0), 255);
    pe[idx] = (d < 128) ? re[r * 128 + d] : ce[c * 128 + (d - 128)];
}

__global__ void qinit_kernel(const float* __restrict__ gq, float* __restrict__ q)
{
    int idx = blockIdx.x * blockDim.x + threadIdx.x;
    if (idx >= B * G * D) return;
    q[idx] = gq[idx % (G * D)];
}

// ---------------------------------------------------------------------------
// Cross-attention: grid (B*H, ceil(G/32)), block 256 (8 warps, 4 queries/warp)
// ---------------------------------------------------------------------------
__global__ void __launch_bounds__(256) attn_kernel(
    const float* __restrict__ Q, const float* __restrict__ KV, float* __restrict__ ctx)
{
    __shared__ float Kt[32][196];
    const int bh = blockIdx.x;
    const int b = bh >> 3, h = bh & 7;
    const int tid = threadIdx.x;
    const int lane = tid & 31, w = tid >> 5;

    const float* KVb = KV + (size_t)b * P * 512;
    for (int i = tid; i < P * 32; i += 256) {
        int p = i >> 5, d = i & 31;
        Kt[d][p] = KVb[(size_t)p * 512 + h * 32 + d] * ATT_SCALE;
    }
    __syncthreads();

    const int g0 = (blockIdx.y * 8 + w) * 4;
    if (g0 >= G) return;

    float qr[4];
#pragma unroll
    for (int i = 0; i < 4; i++)
        qr[i] = Q[(size_t)(b * G + g0 + i) * 256 + h * 32 + lane];

    float sc[4][7];
#pragma unroll
    for (int i = 0; i < 4; i++)
#pragma unroll
        for (int j = 0; j < 7; j++) sc[i][j] = 0.f;

#pragma unroll 4
    for (int d = 0; d < 32; d++) {
        float k0 = Kt[d][lane];
        float k1 = Kt[d][32 + lane];
        float k2 = Kt[d][64 + lane];
        float k3 = Kt[d][96 + lane];
        float k4 = Kt[d][128 + lane];
        float k5 = Kt[d][160 + lane];
        float k6 = (lane < 4) ? Kt[d][192 + lane] : 0.f;
#pragma unroll
        for (int i = 0; i < 4; i++) {
            float qd = __shfl_sync(0xffffffffu, qr[i], d);
            sc[i][0] = fmaf(qd, k0, sc[i][0]);
            sc[i][1] = fmaf(qd, k1, sc[i][1]);
            sc[i][2] = fmaf(qd, k2, sc[i][2]);
            sc[i][3] = fmaf(qd, k3, sc[i][3]);
            sc[i][4] = fmaf(qd, k4, sc[i][4]);
            sc[i][5] = fmaf(qd, k5, sc[i][5]);
            sc[i][6] = fmaf(qd, k6, sc[i][6]);
        }
    }

#pragma unroll
    for (int i = 0; i < 4; i++) {
        if (lane >= 4) sc[i][6] = -1e30f;
        float m = sc[i][0];
#pragma unroll
        for (int j = 1; j < 7; j++) m = fmaxf(m, sc[i][j]);
#pragma unroll
        for (int o = 16; o; o >>= 1) m = fmaxf(m, __shfl_xor_sync(0xffffffffu, m, o));
        float s = 0.f;
#pragma unroll
        for (int j = 0; j < 7; j++) { float e = __expf(sc[i][j] - m); sc[i][j] = e; s += e; }
#pragma unroll
        for (int o = 16; o; o >>= 1) s += __shfl_xor_sync(0xffffffffu, s, o);
        float inv = 1.0f / s;
#pragma unroll
        for (int j = 0; j < 7; j++) sc[i][j] *= inv;
    }

    float cx[4] = {0.f, 0.f, 0.f, 0.f};
    const float* Vb = KVb + 256 + h * 32 + lane;
#pragma unroll
    for (int jj = 0; jj < 7; jj++) {
        const int kmax = (jj == 6) ? 4 : 32;
        for (int src = 0; src < kmax; src++) {
            float v = Vb[(size_t)(jj * 32 + src) * 512];
#pragma unroll
            for (int i = 0; i < 4; i++) {
                float a = __shfl_sync(0xffffffffu, sc[i][jj], src);
                cx[i] = fmaf(a, v, cx[i]);
            }
        }
    }
#pragma unroll
    for (int i = 0; i < 4; i++)
        ctx[(size_t)(b * G + g0 + i) * 256 + h * 32 + lane] = cx[i];
}

// ---------------------------------------------------------------------------
// out[b,p,g,:] = softplus(q_proj[b,g,:] + p_proj[b,p,:])
// ---------------------------------------------------------------------------
__global__ void __launch_bounds__(256) head_kernel(
    const float* __restrict__ qp, const float* __restrict__ pp, float* __restrict__ out)
{
    const int bp = blockIdx.y;
    const int b = (bp >= P) ? 1 : 0;
    const int g = blockIdx.x * 8 + (threadIdx.x >> 5);
    const int hh = (threadIdx.x & 31) << 2;
    float4 pv = *(const float4*)(pp + (size_t)bp * HALF + hh);
    float4 qv = *(const float4*)(qp + (size_t)(b * G + g) * HALF + hh);
    float4 o;
    o.x = softplusf(pv.x + qv.x);
    o.y = softplusf(pv.y + qv.y);
    o.z = softplusf(pv.z + qv.z);
    o.w = softplusf(pv.w + qv.w);
    *(float4*)(out + ((size_t)bp * G + g) * HALF + hh) = o;
}

// ---------------------------------------------------------------------------
static inline void sgemm(const float* A, const float* Wt, const float* bias, const float* R,
                         float* C, int M, int N, int K, int act)
{
    if (M >= 1024) {
        dim3 grid(N / 64, (M + 63) / 64);
        sgemm_kernel<64><<<grid, 256>>>(A, Wt, bias, R, C, M, N, K, act);
    } else {
        dim3 grid(N / 64, (M + 31) / 32);
        sgemm_kernel<32><<<grid, 256>>>(A, Wt, bias, R, C, M, N, K, act);
    }
}

static inline void ln(const float* x, const float* r, const float* g, const float* b,
                      float* y, int rows)
{
    ln_kernel<<<(rows + 7) / 8, 256>>>(x, r, g, b, y, rows);
}

extern "C" void kernel_launch(void* const* d_in, const int* in_sizes, int n_in,
                              void* d_out, int out_size)
{
    (void)in_sizes; (void)n_in; (void)out_size;
    const float* patch_features = (const float*)d_in[0];
    const int*   patch_coords   = (const int*)d_in[1];
    const float* patch_proj_w   = (const float*)d_in[2];
    const float* patch_proj_b   = (const float*)d_in[3];
    const float* patch_ln_g     = (const float*)d_in[4];
    const float* patch_ln_b     = (const float*)d_in[5];
    const float* row_embed      = (const float*)d_in[6];
    const float* col_embed      = (const float*)d_in[7];
    const float* pe_proj_w      = (const float*)d_in[8];
    const float* pe_proj_b      = (const float*)d_in[9];
    const float* gene_queries   = (const float*)d_in[10];
    const float* in_proj_w      = (const float*)d_in[11];
    const float* in_proj_b      = (const float*)d_in[12];
    const float* out_w          = (const float*)d_in[13];
    const float* out_b          = (const float*)d_in[14];
    const float* ff1_w          = (const float*)d_in[15];
    const float* ff1_b          = (const float*)d_in[16];
    const float* ff2_w          = (const float*)d_in[17];
    const float* ff2_b          = (const float*)d_in[18];
    const float* ln1_g          = (const float*)d_in[19];
    const float* ln1_b          = (const float*)d_in[20];
    const float* ln2_g          = (const float*)d_in[21];
    const float* ln2_b          = (const float*)d_in[22];
    const float* head_w1        = (const float*)d_in[23];
    const float* head_b1        = (const float*)d_in[24];
    float* out = (float*)d_out;

    float* ws = nullptr;
    cudaGetSymbolAddress((void**)&ws, g_ws);
    float* patch_emb = ws + OFF_PATCH;
    float* tmp       = ws + OFF_TMP;
    float* pe        = ws + OFF_PE;
    float* kv        = ws + OFF_KV;
    float* q         = ws + OFF_Q;
    float* Qb        = ws + OFF_QB;
    float* ctx       = ws + OFF_CTX;
    float* att       = ws + OFF_ATT;
    float* ffh       = ws + OFF_FFH;
    float* qproj     = ws + OFF_QP;
    float* pproj     = ws + OFF_PP;
    float* wtPatch   = ws + OFF_WT_PATCH;
    float* wtPe      = ws + OFF_WT_PE;
    float* wtWq      = ws + OFF_WT_WQ;
    float* wtWkv     = ws + OFF_WT_WKV;
    float* wtOut     = ws + OFF_WT_OUT;
    float* wtFf1     = ws + OFF_WT_FF1;
    float* wtFf2     = ws + OFF_WT_FF2;
    float* wtHead    = ws + OFF_WT_HEAD;

    // ---- build transpose table (23 segments) ----
    TTable tt;
    int seg = 0, toff = 0;
    auto add = [&](const float* src, float* dst, int N, int K) {
        tt.seg[seg] = { src, dst, N, K, toff };
        toff += (N >> 5) * (K >> 5);
        seg++;
    };
    add(patch_proj_w, wtPatch, 256, 1024);
    add(pe_proj_w,    wtPe,    256, 256);
    for (int l = 0; l < NL; l++) add(in_proj_w + (size_t)l * 3 * D * D,         wtWq  + (size_t)l * 256 * 256, 256, 256);
    for (int l = 0; l < NL; l++) add(in_proj_w + (size_t)l * 3 * D * D + D * D, wtWkv + (size_t)l * 512 * 256, 512, 256);
    for (int l = 0; l < NL; l++) add(out_w + (size_t)l * D * D,                 wtOut + (size_t)l * 256 * 256, 256, 256);
    for (int l = 0; l < NL; l++) add(ff1_w + (size_t)l * 4 * D * D,             wtFf1 + (size_t)l * 1024 * 256, 1024, 256);
    for (int l = 0; l < NL; l++) add(ff2_w + (size_t)l * D * 4 * D,             wtFf2 + (size_t)l * 256 * 1024, 256, 1024);
    add(head_w1, wtHead, 128, 256);
    transpose_kernel<<<toff, 256>>>(tt);

    const int MQ = B * G;  // 4000
    const int MP = B * P;  // 392

    // Stage A: patch embedding
    sgemm(patch_features, wtPatch, patch_proj_b, nullptr, tmp, MP, D, FD, 0);
    ln(tmp, nullptr, patch_ln_g, patch_ln_b, patch_emb, MP);
    pe_kernel<<<(B * P * D + 255) / 256, 256>>>(patch_coords, row_embed, col_embed, pe);
    sgemm(pe, wtPe, pe_proj_b, patch_emb, patch_emb, MP, D, D, 0);
    qinit_kernel<<<(B * G * D + 255) / 256, 256>>>(gene_queries, q);

    // Stage B: decoder layers
    for (int l = 0; l < NL; l++) {
        const float* bq  = in_proj_b + (size_t)l * 3 * D;
        const float* bkv = bq + D;
        sgemm(q, wtWq + (size_t)l * 256 * 256, bq, nullptr, Qb, MQ, D, D, 0);
        sgemm(patch_emb, wtWkv + (size_t)l * 512 * 256, bkv, nullptr, kv, MP, 2 * D, D, 0);
        attn_kernel<<<dim3(B * H, (G + 31) / 32), 256>>>(Qb, kv, ctx);
        sgemm(ctx, wtOut + (size_t)l * 256 * 256, out_b + (size_t)l * D, nullptr, att, MQ, D, D, 0);
        ln(q, att, ln1_g + (size_t)l * D, ln1_b + (size_t)l * D, q, MQ);
        sgemm(q, wtFf1 + (size_t)l * 1024 * 256, ff1_b + (size_t)l * 4 * D, nullptr, ffh, MQ, 4 * D, D, 1);
        sgemm(ffh, wtFf2 + (size_t)l * 256 * 1024, ff2_b + (size_t)l * D, nullptr, att, MQ, D, 4 * D, 0);
        ln(q, att, ln2_g + (size_t)l * D, ln2_b + (size_t)l * D, q, MQ);
    }

    // Stage C: head + broadcast softplus epilogue
    sgemm(q, wtHead, head_b1, nullptr, qproj, MQ, HALF, D, 0);
    sgemm(patch_emb, wtHead, nullptr, nullptr, pproj, MP, HALF, D, 0);
    head_kernel<<<dim3(G / 8, B * P), 256>>>(qproj, pproj, out);
}

// round 6
// speedup vs baseline: 1.5734x; 1.2603x over previous
#include <cuda_runtime.h>
#include <cuda_bf16.h>
#include <cstddef>
#include <cstdint>
#include <math.h>

// ---------------------------------------------------------------------------
// SpatialTranscriptomicsDecoder — GB300 sm_103a. Round 6.
// Big GEMMs (M=4000): mma.sync bf16 (HMMA) with bf16x2-split 3-term compensation.
// Small GEMMs (M=392): fp32 FMA path.
// ---------------------------------------------------------------------------

static constexpr int B = 2, P = 196, FD = 1024, G = 2000, D = 256, H = 8, NL = 4, HALF = 128;
static constexpr float ATT_SCALE = 0.17677669529663687f;
static constexpr int MQ = B * G;   // 4000
static constexpr int MP = B * P;   // 392

// ---------------- fp32 workspace ----------------
static constexpr size_t OFF_PATCH = 0;
static constexpr size_t OFF_TMP   = OFF_PATCH + (size_t)MP * D;
static constexpr size_t OFF_PE    = OFF_TMP   + (size_t)MP * D;
static constexpr size_t OFF_KV    = OFF_PE    + (size_t)MP * D;
static constexpr size_t OFF_Q     = OFF_KV    + (size_t)MP * 2 * D;
static constexpr size_t OFF_QB    = OFF_Q     + (size_t)MQ * D;
static constexpr size_t OFF_ATT   = OFF_QB    + (size_t)MQ * D;
static constexpr size_t OFF_QP    = OFF_ATT   + (size_t)MQ * D;
static constexpr size_t OFF_PP    = OFF_QP    + (size_t)MQ * HALF;
static constexpr size_t OFF_WT_PATCH = OFF_PP + (size_t)MP * HALF;
static constexpr size_t OFF_WT_PE    = OFF_WT_PATCH + 256 * 1024;
static constexpr size_t OFF_WT_WKV   = OFF_WT_PE    + 256 * 256;
static constexpr size_t OFF_WT_HEAD  = OFF_WT_WKV   + (size_t)NL * 512 * 256;
static constexpr size_t WS_TOTAL     = OFF_WT_HEAD  + 128 * 256;
__device__ float g_ws[WS_TOTAL];

// ---------------- bf16 workspace ----------------
static constexpr size_t BQ  = (size_t)MQ * D;
static constexpr size_t BF_QH  = 0;
static constexpr size_t BF_QL  = BF_QH + BQ;
static constexpr size_t BF_L1H = BF_QL + BQ;
static constexpr size_t BF_L1L = BF_L1H + BQ;
static constexpr size_t BF_CXH = BF_L1L + BQ;
static constexpr size_t BF_CXL = BF_CXH + BQ;
static constexpr size_t BF_FH  = BF_CXL + BQ;
static constexpr size_t BF_FL  = BF_FH + (size_t)MQ * 4 * D;
static constexpr size_t BF_WQH = BF_FL + (size_t)MQ * 4 * D;
static constexpr size_t BF_WQL = BF_WQH + (size_t)NL * D * D;
static constexpr size_t BF_WOH = BF_WQL + (size_t)NL * D * D;
static constexpr size_t BF_WOL = BF_WOH + (size_t)NL * D * D;
static constexpr size_t BF_F1H = BF_WOL + (size_t)NL * D * D;
static constexpr size_t BF_F1L = BF_F1H + (size_t)NL * 4 * D * D;
static constexpr size_t BF_F2H = BF_F1L + (size_t)NL * 4 * D * D;
static constexpr size_t BF_F2L = BF_F2H + (size_t)NL * 4 * D * D;
static constexpr size_t BF_HDH = BF_F2L + (size_t)NL * 4 * D * D;
static constexpr size_t BF_HDL = BF_HDH + (size_t)HALF * D;
static constexpr size_t BF_TOTAL = BF_HDL + (size_t)HALF * D;
__device__ __nv_bfloat16 g_bf[BF_TOTAL];

// ---------------- helpers ----------------
__device__ __forceinline__ float geluf(float x) {
    return 0.5f * x * (1.0f + erff(x * 0.7071067811865476f));
}
__device__ __forceinline__ float softplusf(float x) {
    return fmaxf(x, 0.0f) + __logf(1.0f + __expf(-fabsf(x)));
}
__device__ __forceinline__ void splitf(float v, __nv_bfloat16& h, __nv_bfloat16& l) {
    h = __float2bfloat16(v);
    l = __float2bfloat16(v - __bfloat162float(h));
}
__device__ __forceinline__ float2 u2f2(unsigned long long u) {
    float2 f;
    asm("mov.b64 {%0, %1}, %2;" : "=f"(f.x), "=f"(f.y) : "l"(u));
    return f;
}
__device__ __forceinline__ void fma2(unsigned long long& acc, unsigned long long a,
                                     unsigned long long b) {
    asm("fma.rn.f32x2 %0, %1, %2, %0;" : "+l"(acc) : "l"(a), "l"(b));
}
__device__ __forceinline__ void cpa16(unsigned int dst, const void* src, bool ok) {
    asm volatile("cp.async.ca.shared.global [%0], [%1], 16, %2;"
                 :: "r"(dst), "l"(src), "r"(ok ? 16 : 0) : "memory");
}
__device__ __forceinline__ void cpa_commit() {
    asm volatile("cp.async.commit_group;" ::: "memory");
}
template<int Ng> __device__ __forceinline__ void cpa_waitg() {
    asm volatile("cp.async.wait_group %0;" :: "n"(Ng) : "memory");
}
__device__ __forceinline__ void ldm4(unsigned& r0, unsigned& r1, unsigned& r2, unsigned& r3,
                                     unsigned addr) {
    asm volatile("ldmatrix.sync.aligned.m8n8.x4.shared.b16 {%0,%1,%2,%3}, [%4];"
                 : "=r"(r0), "=r"(r1), "=r"(r2), "=r"(r3) : "r"(addr));
}
__device__ __forceinline__ void mma16816(float* d, const unsigned* a, unsigned b0, unsigned b1) {
    asm volatile(
        "mma.sync.aligned.m16n8k16.row.col.f32.bf16.bf16.f32 "
        "{%0,%1,%2,%3}, {%4,%5,%6,%7}, {%8,%9}, {%0,%1,%2,%3};"
        : "+f"(d[0]), "+f"(d[1]), "+f"(d[2]), "+f"(d[3])
        : "r"(a[0]), "r"(a[1]), "r"(a[2]), "r"(a[3]), "r"(b0), "r"(b1));
}

// ---------------------------------------------------------------------------
// mma.sync GEMM: C[M,N] = act( (Ah+Al) @ (Wh+Wl)^T + bias )
// Ah/Al: [M,K] bf16. Wh/Wl: [N,K] bf16. 3-term: AhBh + AhBl + AlBh.
// grid (N/64, ceil(M/128)), 256 threads (8 warps, 4x2), warp tile 32x32.
// act 0 -> Cf fp32; act 1 -> GELU + split into Ch/Cl.
// ---------------------------------------------------------------------------
__global__ void __launch_bounds__(256) mma_gemm_kernel(
    const __nv_bfloat16* __restrict__ Ah, const __nv_bfloat16* __restrict__ Al,
    const __nv_bfloat16* __restrict__ Wh, const __nv_bfloat16* __restrict__ Wl,
    const float* __restrict__ bias,
    float* __restrict__ Cf, __nv_bfloat16* __restrict__ Ch, __nv_bfloat16* __restrict__ Cl,
    int M, int N, int K, int act)
{
    // row stride 24 bf16 (48B): conflict-free ldmatrix, 16B-aligned segments
    __shared__ __align__(16) __nv_bfloat16 sAh[2][128][24];
    __shared__ __align__(16) __nv_bfloat16 sAl[2][128][24];
    __shared__ __align__(16) __nv_bfloat16 sWh[2][64][24];
    __shared__ __align__(16) __nv_bfloat16 sWl[2][64][24];

    const int tid = threadIdx.x;
    const int lane = tid & 31, wid = tid >> 5;
    const int wm = wid & 3, wn = wid >> 2;          // warp tile origin (wm*32, wn*32)
    const int bm = blockIdx.y * 128;
    const int bn = blockIdx.x * 64;
    const int NC = K >> 4;

    // ---- loader setup ----
    const int rowA = tid >> 1, segA = tid & 1;       // A: 128 rows x 2 segs
    const bool a_ok = (bm + rowA) < M;
    const __nv_bfloat16* srcAh = Ah + (size_t)(bm + rowA) * K + segA * 8;
    const __nv_bfloat16* srcAl = Al + (size_t)(bm + rowA) * K + segA * 8;
    const int rowW = (tid & 127) >> 1, segW = tid & 1; // W: 64 rows x 2 segs, split h/l by tid<128
    const __nv_bfloat16* srcW = ((tid < 128) ? Wh : Wl) + (size_t)(bn + rowW) * K + segW * 8;

    unsigned dAh[2], dAl[2], dW[2];
#pragma unroll
    for (int b = 0; b < 2; b++) {
        dAh[b] = (unsigned)__cvta_generic_to_shared(&sAh[b][rowA][segA * 8]);
        dAl[b] = (unsigned)__cvta_generic_to_shared(&sAl[b][rowA][segA * 8]);
        dW[b]  = (unsigned)__cvta_generic_to_shared(
                     tid < 128 ? &sWh[b][rowW][segW * 8] : &sWl[b][rowW][segW * 8]);
    }

    // ---- ldmatrix addresses ----
    // A frag (m16k16): row = wm*32 + mt*16 + (lane&15), kbyte = (lane>>4)*16
    // B frag x4 (2 n-tiles): n = wn*32 + np*16 + (lane&7) + ((lane>>4)<<3), kbyte = ((lane>>3)&1)*16
    unsigned lAh[2][2], lAl[2][2], lWh[2][2], lWl[2][2];
    {
        const int ar = wm * 32 + (lane & 15);
        const int ak = (lane >> 4) * 8;
        const int brr = wn * 32 + (lane & 7) + ((lane >> 4) << 3);
        const int bk = ((lane >> 3) & 1) * 8;
#pragma unroll
        for (int b = 0; b < 2; b++) {
#pragma unroll
            for (int t = 0; t < 2; t++) {
                lAh[b][t] = (unsigned)__cvta_generic_to_shared(&sAh[b][ar + t * 16][ak]);
                lAl[b][t] = (unsigned)__cvta_generic_to_shared(&sAl[b][ar + t * 16][ak]);
                lWh[b][t] = (unsigned)__cvta_generic_to_shared(&sWh[b][brr + t * 16][bk]);
                lWl[b][t] = (unsigned)__cvta_generic_to_shared(&sWl[b][brr + t * 16][bk]);
            }
        }
    }

    auto loadChunk = [&](int kc, int buf) {
        const int o = kc << 4;
        cpa16(dAh[buf], srcAh + o, a_ok);
        cpa16(dAl[buf], srcAl + o, a_ok);
        cpa16(dW[buf], srcW + o, true);
        cpa_commit();
    };

    loadChunk(0, 0);
    if (NC > 1) loadChunk(1, 1);

    float acc[2][4][4];
#pragma unroll
    for (int i = 0; i < 2; i++)
#pragma unroll
        for (int j = 0; j < 4; j++)
#pragma unroll
            for (int k = 0; k < 4; k++) acc[i][j][k] = 0.f;

    for (int kc = 0; kc < NC; kc++) {
        if (kc + 1 < NC) cpa_waitg<1>(); else cpa_waitg<0>();
        __syncthreads();
        const int buf = kc & 1;

        unsigned ah[2][4], al[2][4], bh[2][4], bl[2][4];
#pragma unroll
        for (int t = 0; t < 2; t++) {
            ldm4(ah[t][0], ah[t][1], ah[t][2], ah[t][3], lAh[buf][t]);
            ldm4(al[t][0], al[t][1], al[t][2], al[t][3], lAl[buf][t]);
            ldm4(bh[t][0], bh[t][1], bh[t][2], bh[t][3], lWh[buf][t]);
            ldm4(bl[t][0], bl[t][1], bl[t][2], bl[t][3], lWl[buf][t]);
        }
#pragma unroll
        for (int mt = 0; mt < 2; mt++) {
#pragma unroll
            for (int nt = 0; nt < 4; nt++) {
                const int np = nt >> 1, nh = (nt & 1) << 1;
                mma16816(acc[mt][nt], ah[mt], bh[np][nh], bh[np][nh + 1]);
                mma16816(acc[mt][nt], ah[mt], bl[np][nh], bl[np][nh + 1]);
                mma16816(acc[mt][nt], al[mt], bh[np][nh], bh[np][nh + 1]);
            }
        }
        __syncthreads();
        if (kc + 2 < NC) loadChunk(kc + 2, buf);
    }

    // ---- epilogue ----
    // d0,d1: row = lane>>2, cols 2*(lane&3)+{0,1}; d2,d3: row+8
    const int rowb = bm + wm * 32 + (lane >> 2);
    const int colb = bn + wn * 32 + 2 * (lane & 3);
#pragma unroll
    for (int mt = 0; mt < 2; mt++) {
#pragma unroll
        for (int nt = 0; nt < 4; nt++) {
            const int col = colb + nt * 8;
            float2 b2 = make_float2(0.f, 0.f);
            if (bias) b2 = *(const float2*)(bias + col);
#pragma unroll
            for (int hh = 0; hh < 2; hh++) {
                const int row = rowb + mt * 16 + hh * 8;
                if (row >= M) continue;
                float v0 = acc[mt][nt][hh * 2 + 0] + b2.x;
                float v1 = acc[mt][nt][hh * 2 + 1] + b2.y;
                if (act == 0) {
                    *(float2*)(Cf + (size_t)row * N + col) = make_float2(v0, v1);
                } else {
                    v0 = geluf(v0); v1 = geluf(v1);
                    __nv_bfloat16 h0, l0, h1, l1;
                    splitf(v0, h0, l0);
                    splitf(v1, h1, l1);
                    *(__nv_bfloat162*)(Ch + (size_t)row * N + col) = __nv_bfloat162(h0, h1);
                    *(__nv_bfloat162*)(Cl + (size_t)row * N + col) = __nv_bfloat162(l0, l1);
                }
            }
        }
    }
}

// ---------------------------------------------------------------------------
// weight split: fp32 -> bf16 hi/lo, 17 segments
// ---------------------------------------------------------------------------
struct CSeg { const float* src; __nv_bfloat16* h; __nv_bfloat16* l; int blk_off; };
struct CTable { CSeg seg[17]; };
__global__ void __launch_bounds__(256) wsplit_kernel(CTable t)
{
    const int bt = blockIdx.x;
    int s = 0;
#pragma unroll
    for (int i = 1; i < 17; i++) if (t.seg[i].blk_off <= bt) s = i;
    const CSeg sg = t.seg[s];
    const int idx = (bt - sg.blk_off) * 1024 + threadIdx.x * 4;
    float4 v = *(const float4*)(sg.src + idx);
    __nv_bfloat16 h, l;
    splitf(v.x, h, l); sg.h[idx + 0] = h; sg.l[idx + 0] = l;
    splitf(v.y, h, l); sg.h[idx + 1] = h; sg.l[idx + 1] = l;
    splitf(v.z, h, l); sg.h[idx + 2] = h; sg.l[idx + 2] = l;
    splitf(v.w, h, l); sg.h[idx + 3] = h; sg.l[idx + 3] = l;
}

// ---------------------------------------------------------------------------
// transpose for FMA-path weights: src[N,K] -> dst[K,N]; 7 segments
// ---------------------------------------------------------------------------
struct TSeg { const float* src; float* dst; int N; int K; int tile_off; };
struct TTable { TSeg seg[7]; };
__global__ void __launch_bounds__(256) transpose_kernel(TTable t)
{
    __shared__ float sm[32][33];
    const int bt = blockIdx.x;
    int s = 0;
#pragma unroll
    for (int i = 1; i < 7; i++) if (t.seg[i].tile_off <= bt) s = i;
    const TSeg sg = t.seg[s];
    const int lt = bt - sg.tile_off;
    const int tk = sg.K >> 5;
    const int nr = (lt / tk) << 5;
    const int kc = (lt % tk) << 5;
    const int tx = threadIdx.x & 31, ty = threadIdx.x >> 5;
#pragma unroll
    for (int i = 0; i < 4; i++)
        sm[ty + i * 8][tx] = sg.src[(size_t)(nr + ty + i * 8) * sg.K + kc + tx];
    __syncthreads();
#pragma unroll
    for (int i = 0; i < 4; i++)
        sg.dst[(size_t)(kc + ty + i * 8) * sg.N + nr + tx] = sm[tx][ty + i * 8];
}

// ---------------------------------------------------------------------------
// FMA sgemm (small M)
// ---------------------------------------------------------------------------
__global__ void __launch_bounds__(256) sgemm_kernel(
    const float* __restrict__ A, const float* __restrict__ Wt,
    const float* __restrict__ bias, const float* __restrict__ R,
    float* __restrict__ C, int M, int N, int K, int act)
{
    constexpr int BM = 32, RPT = 2, S = 4;
    __shared__ __align__(16) float As[S][BM][20];
    __shared__ __align__(16) float Ws[S][16][68];
    const int tid = threadIdx.x;
    const int tx = tid & 15;
    const int ty = tid >> 4;
    const int bm = blockIdx.y * BM;
    const int bn = blockIdx.x * 64;
    const int kkW = tid >> 4;
    const int nW  = (tid & 15) << 2;
    const float* WtBase = Wt + (size_t)kkW * N + bn + nW;
    const int rA = tid >> 2;
    const int cA = (tid & 3) << 2;
    const bool a_thread = (tid < 128);
    const bool a_ok = a_thread && (bm + rA) < M;
    const float* Ap = A + (size_t)(bm + rA) * K + cA;

    unsigned int sW[S], sA[S];
#pragma unroll
    for (int s = 0; s < S; s++) {
        sW[s] = (unsigned int)__cvta_generic_to_shared(&Ws[s][kkW][nW]);
        sA[s] = (unsigned int)__cvta_generic_to_shared(&As[s][rA & (BM - 1)][cA]);
    }
    const int niter = K >> 4;
#pragma unroll
    for (int s = 0; s < S - 1; s++) {
        const int k0 = s << 4;
        cpa16(sW[s], WtBase + (size_t)k0 * N, true);
        if (a_thread) cpa16(sA[s], Ap + k0, a_ok);
        cpa_commit();
    }
    unsigned long long acc[RPT][2];
#pragma unroll
    for (int i = 0; i < RPT; i++) { acc[i][0] = 0ull; acc[i][1] = 0ull; }

    for (int it = 0; it < niter; it++) {
        cpa_waitg<2>();
        __syncthreads();
        const int nit = it + S - 1;
        if (nit < niter) {
            const int nb = nit & (S - 1);
            const int k0 = nit << 4;
            cpa16(sW[nb], WtBase + (size_t)k0 * N, true);
            if (a_thread) cpa16(sA[nb], Ap + k0, a_ok);
        }
        cpa_commit();
        const int buf = it & (S - 1);
#pragma unroll
        for (int kk = 0; kk < 16; kk++) {
            ulonglong2 bb = *(const ulonglong2*)&Ws[buf][kk][tx << 2];
#pragma unroll
            for (int i = 0; i < RPT; i++) {
                float a = As[buf][ty * RPT + i][kk];
                unsigned long long a2;
                asm("mov.b64 %0, {%1, %1};" : "=l"(a2) : "f"(a));
                fma2(acc[i][0], a2, bb.x);
                fma2(acc[i][1], a2, bb.y);
            }
        }
    }
    const int col0 = bn + (tx << 2);
    float4 b4 = make_float4(0.f, 0.f, 0.f, 0.f);
    if (bias) b4 = *(const float4*)(bias + col0);
#pragma unroll
    for (int i = 0; i < RPT; i++) {
        int row = bm + ty * RPT + i;
        if (row >= M) continue;
        float2 v0 = u2f2(acc[i][0]);
        float2 v1 = u2f2(acc[i][1]);
        float4 o;
        o.x = v0.x + b4.x; o.y = v0.y + b4.y; o.z = v1.x + b4.z; o.w = v1.y + b4.w;
        if (R) {
            float4 r4 = *(const float4*)(R + (size_t)row * N + col0);
            o.x += r4.x; o.y += r4.y; o.z += r4.z; o.w += r4.w;
        }
        if (act == 1) { o.x = geluf(o.x); o.y = geluf(o.y); o.z = geluf(o.z); o.w = geluf(o.w); }
        *(float4*)(C + (size_t)row * N + col0) = o;
    }
}

// ---------------------------------------------------------------------------
// LN (+optional bf16 hi/lo emit)
// ---------------------------------------------------------------------------
__global__ void ln_kernel(const float* __restrict__ x, const float* __restrict__ r,
                          const float* __restrict__ gg, const float* __restrict__ bb,
                          float* __restrict__ y,
                          __nv_bfloat16* __restrict__ yh, __nv_bfloat16* __restrict__ yl,
                          int rows)
{
    int gid = blockIdx.x * blockDim.x + threadIdx.x;
    int row = gid >> 5;
    int lane = gid & 31;
    if (row >= rows) return;
    const float* xp = x + (size_t)row * 256;
    float4 a = *(const float4*)(xp + lane * 4);
    float4 c = *(const float4*)(xp + 128 + lane * 4);
    if (r) {
        const float* rp = r + (size_t)row * 256;
        float4 ra = *(const float4*)(rp + lane * 4);
        float4 rc = *(const float4*)(rp + 128 + lane * 4);
        a.x += ra.x; a.y += ra.y; a.z += ra.z; a.w += ra.w;
        c.x += rc.x; c.y += rc.y; c.z += rc.z; c.w += rc.w;
    }
    float s = a.x + a.y + a.z + a.w + c.x + c.y + c.z + c.w;
    float q = a.x * a.x + a.y * a.y + a.z * a.z + a.w * a.w
            + c.x * c.x + c.y * c.y + c.z * c.z + c.w * c.w;
#pragma unroll
    for (int o = 16; o; o >>= 1) {
        s += __shfl_xor_sync(0xffffffffu, s, o);
        q += __shfl_xor_sync(0xffffffffu, q, o);
    }
    float mean = s * (1.f / 256.f);
    float var = q * (1.f / 256.f) - mean * mean;
    float rstd = rsqrtf(var + 1e-5f);
    float4 g0 = *(const float4*)(gg + lane * 4);
    float4 g1 = *(const float4*)(gg + 128 + lane * 4);
    float4 b0 = *(const float4*)(bb + lane * 4);
    float4 b1 = *(const float4*)(bb + 128 + lane * 4);
    float4 o0, o1;
    o0.x = (a.x - mean) * rstd * g0.x + b0.x;
    o0.y = (a.y - mean) * rstd * g0.y + b0.y;
    o0.z = (a.z - mean) * rstd * g0.z + b0.z;
    o0.w = (a.w - mean) * rstd * g0.w + b0.w;
    o1.x = (c.x - mean) * rstd * g1.x + b1.x;
    o1.y = (c.y - mean) * rstd * g1.y + b1.y;
    o1.z = (c.z - mean) * rstd * g1.z + b1.z;
    o1.w = (c.w - mean) * rstd * g1.w + b1.w;
    float* yp = y + (size_t)row * 256;
    *(float4*)(yp + lane * 4) = o0;
    *(float4*)(yp + 128 + lane * 4) = o1;
    if (yh) {
        const float ov[8] = {o0.x, o0.y, o0.z, o0.w, o1.x, o1.y, o1.z, o1.w};
#pragma unroll
        for (int i = 0; i < 8; i++) {
            int col = (i < 4) ? (lane * 4 + i) : (128 + lane * 4 + i - 4);
            __nv_bfloat16 h, l;
            splitf(ov[i], h, l);
            yh[(size_t)row * 256 + col] = h;
            yl[(size_t)row * 256 + col] = l;
        }
    }
}

__global__ void pe_kernel(const int* __restrict__ coords, const float* __restrict__ re,
                          const float* __restrict__ ce, float* __restrict__ pe)
{
    int idx = blockIdx.x * blockDim.x + threadIdx.x;
    if (idx >= B * P * D) return;
    int d = idx & 255;
    int bp = idx >> 8;
    int r = coords[bp * 2 + 0];
    int c = coords[bp * 2 + 1];
    r = min(max(r, 0), 255);
    c = min(max(c, 0), 255);
    pe[idx] = (d < 128) ? re[r * 128 + d] : ce[c * 128 + (d - 128)];
}

__global__ void qinit_kernel(const float* __restrict__ gq, float* __restrict__ q,
                             __nv_bfloat16* __restrict__ qh, __nv_bfloat16* __restrict__ ql)
{
    int idx = blockIdx.x * blockDim.x + threadIdx.x;
    if (idx >= B * G * D) return;
    float v = gq[idx % (G * D)];
    q[idx] = v;
    __nv_bfloat16 h, l;
    splitf(v, h, l);
    qh[idx] = h;
    ql[idx] = l;
}

// ---------------------------------------------------------------------------
// Cross-attention; outputs bf16 hi/lo context for out-projection.
// ---------------------------------------------------------------------------
__global__ void __launch_bounds__(256) attn_kernel(
    const float* __restrict__ Q, const float* __restrict__ KV,
    __nv_bfloat16* __restrict__ cxh, __nv_bfloat16* __restrict__ cxl)
{
    __shared__ float Kt[32][196];
    const int bh = blockIdx.x;
    const int b = bh >> 3, h = bh & 7;
    const int tid = threadIdx.x;
    const int lane = tid & 31, w = tid >> 5;

    const float* KVb = KV + (size_t)b * P * 512;
    for (int i = tid; i < P * 32; i += 256) {
        int p = i >> 5, d = i & 31;
        Kt[d][p] = KVb[(size_t)p * 512 + h * 32 + d] * ATT_SCALE;
    }
    __syncthreads();

    const int g0 = (blockIdx.y * 8 + w) * 4;
    if (g0 >= G) return;

    float qr[4];
#pragma unroll
    for (int i = 0; i < 4; i++)
        qr[i] = Q[(size_t)(b * G + g0 + i) * 256 + h * 32 + lane];

    float sc[4][7];
#pragma unroll
    for (int i = 0; i < 4; i++)
#pragma unroll
        for (int j = 0; j < 7; j++) sc[i][j] = 0.f;

#pragma unroll 4
    for (int d = 0; d < 32; d++) {
        float k0 = Kt[d][lane];
        float k1 = Kt[d][32 + lane];
        float k2 = Kt[d][64 + lane];
        float k3 = Kt[d][96 + lane];
        float k4 = Kt[d][128 + lane];
        float k5 = Kt[d][160 + lane];
        float k6 = (lane < 4) ? Kt[d][192 + lane] : 0.f;
#pragma unroll
        for (int i = 0; i < 4; i++) {
            float qd = __shfl_sync(0xffffffffu, qr[i], d);
            sc[i][0] = fmaf(qd, k0, sc[i][0]);
            sc[i][1] = fmaf(qd, k1, sc[i][1]);
            sc[i][2] = fmaf(qd, k2, sc[i][2]);
            sc[i][3] = fmaf(qd, k3, sc[i][3]);
            sc[i][4] = fmaf(qd, k4, sc[i][4]);
            sc[i][5] = fmaf(qd, k5, sc[i][5]);
            sc[i][6] = fmaf(qd, k6, sc[i][6]);
        }
    }

#pragma unroll
    for (int i = 0; i < 4; i++) {
        if (lane >= 4) sc[i][6] = -1e30f;
        float m = sc[i][0];
#pragma unroll
        for (int j = 1; j < 7; j++) m = fmaxf(m, sc[i][j]);
#pragma unroll
        for (int o = 16; o; o >>= 1) m = fmaxf(m, __shfl_xor_sync(0xffffffffu, m, o));
        float s = 0.f;
#pragma unroll
        for (int j = 0; j < 7; j++) { float e = __expf(sc[i][j] - m); sc[i][j] = e; s += e; }
#pragma unroll
        for (int o = 16; o; o >>= 1) s += __shfl_xor_sync(0xffffffffu, s, o);
        float inv = 1.0f / s;
#pragma unroll
        for (int j = 0; j < 7; j++) sc[i][j] *= inv;
    }

    float cx[4] = {0.f, 0.f, 0.f, 0.f};
    const float* Vb = KVb + 256 + h * 32 + lane;
#pragma unroll
    for (int jj = 0; jj < 7; jj++) {
        const int kmax = (jj == 6) ? 4 : 32;
        for (int src = 0; src < kmax; src++) {
            float v = Vb[(size_t)(jj * 32 + src) * 512];
#pragma unroll
            for (int i = 0; i < 4; i++) {
                float a = __shfl_sync(0xffffffffu, sc[i][jj], src);
                cx[i] = fmaf(a, v, cx[i]);
            }
        }
    }
#pragma unroll
    for (int i = 0; i < 4; i++) {
        size_t off = (size_t)(b * G + g0 + i) * 256 + h * 32 + lane;
        __nv_bfloat16 hh, ll;
        splitf(cx[i], hh, ll);
        cxh[off] = hh;
        cxl[off] = ll;
    }
}

__global__ void __launch_bounds__(256) head_kernel(
    const float* __restrict__ qp, const float* __restrict__ pp, float* __restrict__ out)
{
    const int bp = blockIdx.y;
    const int b = (bp >= P) ? 1 : 0;
    const int g = blockIdx.x * 8 + (threadIdx.x >> 5);
    const int hh = (threadIdx.x & 31) << 2;
    float4 pv = *(const float4*)(pp + (size_t)bp * HALF + hh);
    float4 qv = *(const float4*)(qp + (size_t)(b * G + g) * HALF + hh);
    float4 o;
    o.x = softplusf(pv.x + qv.x);
    o.y = softplusf(pv.y + qv.y);
    o.z = softplusf(pv.z + qv.z);
    o.w = softplusf(pv.w + qv.w);
    *(float4*)(out + ((size_t)bp * G + g) * HALF + hh) = o;
}

// ---------------------------------------------------------------------------
static inline void sgemm_small(const float* A, const float* Wt, const float* bias,
                               const float* R, float* C, int M, int N, int K, int act)
{
    dim3 grid(N / 64, (M + 31) / 32);
    sgemm_kernel<<<grid, 256>>>(A, Wt, bias, R, C, M, N, K, act);
}

extern "C" void kernel_launch(void* const* d_in, const int* in_sizes, int n_in,
                              void* d_out, int out_size)
{
    (void)in_sizes; (void)n_in; (void)out_size;
    const float* patch_features = (const float*)d_in[0];
    const int*   patch_coords   = (const int*)d_in[1];
    const float* patch_proj_w   = (const float*)d_in[2];
    const float* patch_proj_b   = (const float*)d_in[3];
    const float* patch_ln_g     = (const float*)d_in[4];
    const float* patch_ln_b     = (const float*)d_in[5];
    const float* row_embed      = (const float*)d_in[6];
    const float* col_embed      = (const float*)d_in[7];
    const float* pe_proj_w      = (const float*)d_in[8];
    const float* pe_proj_b      = (const float*)d_in[9];
    const float* gene_queries   = (const float*)d_in[10];
    const float* in_proj_w      = (const float*)d_in[11];
    const float* in_proj_b      = (const float*)d_in[12];
    const float* out_w          = (const float*)d_in[13];
    const float* out_b          = (const float*)d_in[14];
    const float* ff1_w          = (const float*)d_in[15];
    const float* ff1_b          = (const float*)d_in[16];
    const float* ff2_w          = (const float*)d_in[17];
    const float* ff2_b          = (const float*)d_in[18];
    const float* ln1_g          = (const float*)d_in[19];
    const float* ln1_b          = (const float*)d_in[20];
    const float* ln2_g          = (const float*)d_in[21];
    const float* ln2_b          = (const float*)d_in[22];
    const float* head_w1        = (const float*)d_in[23];
    const float* head_b1        = (const float*)d_in[24];
    float* out = (float*)d_out;

    float* ws = nullptr;
    cudaGetSymbolAddress((void**)&ws, g_ws);
    __nv_bfloat16* bf = nullptr;
    cudaGetSymbolAddress((void**)&bf, g_bf);

    float* patch_emb = ws + OFF_PATCH;
    float* tmp       = ws + OFF_TMP;
    float* pe        = ws + OFF_PE;
    float* kv        = ws + OFF_KV;
    float* q         = ws + OFF_Q;
    float* Qb        = ws + OFF_QB;
    float* att       = ws + OFF_ATT;
    float* qproj     = ws + OFF_QP;
    float* pproj     = ws + OFF_PP;
    float* wtPatch   = ws + OFF_WT_PATCH;
    float* wtPe      = ws + OFF_WT_PE;
    float* wtWkv     = ws + OFF_WT_WKV;
    float* wtHead    = ws + OFF_WT_HEAD;

    __nv_bfloat16* qh  = bf + BF_QH;
    __nv_bfloat16* ql  = bf + BF_QL;
    __nv_bfloat16* l1h = bf + BF_L1H;
    __nv_bfloat16* l1l = bf + BF_L1L;
    __nv_bfloat16* cxh = bf + BF_CXH;
    __nv_bfloat16* cxl = bf + BF_CXL;
    __nv_bfloat16* fh  = bf + BF_FH;
    __nv_bfloat16* fl  = bf + BF_FL;

    // ---- one-time weight prep ----
    TTable tt;
    {
        int seg = 0, toff = 0;
        auto add = [&](const float* src, float* dst, int N, int K) {
            tt.seg[seg] = { src, dst, N, K, toff };
            toff += (N >> 5) * (K >> 5);
            seg++;
        };
        add(patch_proj_w, wtPatch, 256, 1024);
        add(pe_proj_w,    wtPe,    256, 256);
        for (int l = 0; l < NL; l++)
            add(in_proj_w + (size_t)l * 3 * D * D + D * D, wtWkv + (size_t)l * 512 * 256, 512, 256);
        add(head_w1, wtHead, 128, 256);
        transpose_kernel<<<toff, 256>>>(tt);
    }
    CTable ct;
    {
        int seg = 0, boff = 0;
        auto add = [&](const float* src, size_t ho, size_t lo, int count) {
            ct.seg[seg] = { src, bf + ho, bf + lo, boff };
            boff += count / 1024;
            seg++;
        };
        for (int l = 0; l < NL; l++)
            add(in_proj_w + (size_t)l * 3 * D * D, BF_WQH + (size_t)l * D * D, BF_WQL + (size_t)l * D * D, D * D);
        for (int l = 0; l < NL; l++)
            add(out_w + (size_t)l * D * D, BF_WOH + (size_t)l * D * D, BF_WOL + (size_t)l * D * D, D * D);
        for (int l = 0; l < NL; l++)
            add(ff1_w + (size_t)l * 4 * D * D, BF_F1H + (size_t)l * 4 * D * D, BF_F1L + (size_t)l * 4 * D * D, 4 * D * D);
        for (int l = 0; l < NL; l++)
            add(ff2_w + (size_t)l * 4 * D * D, BF_F2H + (size_t)l * 4 * D * D, BF_F2L + (size_t)l * 4 * D * D, 4 * D * D);
        add(head_w1, BF_HDH, BF_HDL, HALF * D);
        int total = ct.seg[16].blk_off + (HALF * D) / 1024;
        wsplit_kernel<<<total, 256>>>(ct);
    }

    // ---- Stage A ----
    sgemm_small(patch_features, wtPatch, patch_proj_b, nullptr, tmp, MP, D, FD, 0);
    ln_kernel<<<(MP + 7) / 8, 256>>>(tmp, nullptr, patch_ln_g, patch_ln_b, patch_emb,
                                     nullptr, nullptr, MP);
    pe_kernel<<<(B * P * D + 255) / 256, 256>>>(patch_coords, row_embed, col_embed, pe);
    sgemm_small(pe, wtPe, pe_proj_b, patch_emb, patch_emb, MP, D, D, 0);
    qinit_kernel<<<(MQ * D + 255) / 256, 256>>>(gene_queries, q, qh, ql);

    const int MT = (MQ + 127) / 128;   // 32
    // ---- Stage B: decoder layers ----
    for (int l = 0; l < NL; l++) {
        const float* bq  = in_proj_b + (size_t)l * 3 * D;
        const float* bkv = bq + D;
        mma_gemm_kernel<<<dim3(D / 64, MT), 256>>>(
            qh, ql, bf + BF_WQH + (size_t)l * D * D, bf + BF_WQL + (size_t)l * D * D,
            bq, Qb, nullptr, nullptr, MQ, D, D, 0);
        sgemm_small(patch_emb, wtWkv + (size_t)l * 512 * 256, bkv, nullptr, kv, MP, 2 * D, D, 0);
        attn_kernel<<<dim3(B * H, (G + 31) / 32), 256>>>(Qb, kv, cxh, cxl);
        mma_gemm_kernel<<<dim3(D / 64, MT), 256>>>(
            cxh, cxl, bf + BF_WOH + (size_t)l * D * D, bf + BF_WOL + (size_t)l * D * D,
            out_b + (size_t)l * D, att, nullptr, nullptr, MQ, D, D, 0);
        ln_kernel<<<(MQ + 7) / 8, 256>>>(q, att, ln1_g + (size_t)l * D, ln1_b + (size_t)l * D,
                                         q, l1h, l1l, MQ);
        mma_gemm_kernel<<<dim3(4 * D / 64, MT), 256>>>(
            l1h, l1l, bf + BF_F1H + (size_t)l * 4 * D * D, bf + BF_F1L + (size_t)l * 4 * D * D,
            ff1_b + (size_t)l * 4 * D, nullptr, fh, fl, MQ, 4 * D, D, 1);
        mma_gemm_kernel<<<dim3(D / 64, MT), 256>>>(
            fh, fl, bf + BF_F2H + (size_t)l * 4 * D * D, bf + BF_F2L + (size_t)l * 4 * D * D,
            ff2_b + (size_t)l * D, att, nullptr, nullptr, MQ, D, 4 * D, 0);
        ln_kernel<<<(MQ + 7) / 8, 256>>>(q, att, ln2_g + (size_t)l * D, ln2_b + (size_t)l * D,
                                         q, qh, ql, MQ);
    }

    // ---- Stage C ----
    mma_gemm_kernel<<<dim3(HALF / 64, MT), 256>>>(
        qh, ql, bf + BF_HDH, bf + BF_HDL, head_b1, qproj, nullptr, nullptr, MQ, HALF, D, 0);
    sgemm_small(patch_emb, wtHead, nullptr, nullptr, pproj, MP, HALF, D, 0);
    head_kernel<<<dim3(G / 8, B * P), 256>>>(qproj, pproj, out);
}